// round 6
// baseline (speedup 1.0000x reference)
#include <cuda_runtime.h>

#define FLAT 12288
#define HID  4096
#define NS   16
#define KST  4
#define LRf  0.01f
#define RCH  96          // row chunks for W^T v partials
#define ROWS_PER_CH 128  // RCH * ROWS_PER_CH == FLAT
#define CTH  1024        // cheap-phase threads (single block)

// ---------------- device scratch (static, no runtime allocation) ----------------
__device__ float g_part[RCH * HID];   // gemvT partial column sums
__device__ float g_h[HID];            // dense-phase working h
__device__ float g_hA[HID];           // hinit_0 (q)
__device__ float g_hB[HID];           // hfinal_0 (s)
__device__ float g_hC[HID];           // pong q
__device__ float g_hD[HID];           // pong s
__device__ float g_vA[FLAT];          // vfinal_0 / r ping
__device__ float g_vB[FLAT];          // r pong

__device__ __forceinline__ float sigm(float x) { return 1.f / (1.f + __expf(-x)); }

// ---------------- dense phase: sample 0 with the real W ----------------
// L2 ping-pong: k_gemvT sweeps W rows ASCENDING, k_gemv sweeps DESCENDING.
// Each sweep therefore starts on the ~126MB of W the previous sweep touched
// last (still L2-resident), converting ~60% of 7 of the 8 sweeps to L2 hits.

// partial column sums of W^T v: block = 256 threads x float2 (512 cols),
// blockIdx.y = 128-row chunk, ascending. grid (8, 96) = 768 blocks.
__global__ void k_gemvT(const float* __restrict__ W, const float* __restrict__ v) {
    __shared__ float sv[ROWS_PER_CH];
    int r0 = blockIdx.y * ROWS_PER_CH;
    if (threadIdx.x < ROWS_PER_CH) sv[threadIdx.x] = v[r0 + threadIdx.x];
    __syncthreads();
    int col2 = blockIdx.x * 256 + threadIdx.x;      // float2 column index
    const float2* Wp = (const float2*)W + (size_t)r0 * (HID / 2) + col2;
    float ax = 0.f, ay = 0.f;
#pragma unroll 8
    for (int r = 0; r < ROWS_PER_CH; r++) {
        float2 w = Wp[(size_t)r * (HID / 2)];
        float s = sv[r];
        ax += w.x * s;
        ay += w.y * s;
    }
    float2 o; o.x = ax; o.y = ay;
    ((float2*)g_part)[blockIdx.y * (HID / 2) + col2] = o;
}

// reduce partials + bias + sigmoid -> g_h; optionally save hinit/hfinal
__global__ void k_hred(const float* __restrict__ b, int save) {
    int j = blockIdx.x * 256 + threadIdx.x;
    float s = b[j];
#pragma unroll 8
    for (int r = 0; r < RCH; r++) s += g_part[r * HID + j];
    float h = sigm(s);
    g_h[j] = h;
    if (save == 1) g_hA[j] = h;        // hinit_0 (q for sample 1)
    else if (save == 2) g_hB[j] = h;   // hfinal_0 (s for sample 1)
}

// v = sigmoid(a + W h): one warp per row, 16 rows per 512-thread block,
// row blocks DESCENDING so the sweep starts on L2-hot tail rows of k_gemvT.
__global__ void k_gemv(const float* __restrict__ W, const float* __restrict__ a) {
    __shared__ float sh[HID];
    for (int k = threadIdx.x; k < HID; k += blockDim.x) sh[k] = g_h[k];
    __syncthreads();
    int warp = threadIdx.x >> 5, lane = threadIdx.x & 31;
    int row = (gridDim.x - 1 - blockIdx.x) * 16 + warp;   // descending sweep
    const float4* Wr = (const float4*)(W + (size_t)row * HID);
    float acc = 0.f;
#pragma unroll 8
    for (int i = lane; i < HID / 4; i += 32) {
        float4 w = Wr[i];
        float4 h4 = *(const float4*)&sh[4 * i];
        acc += w.x * h4.x + w.y * h4.y + w.z * h4.z + w.w * h4.w;
    }
#pragma unroll
    for (int o = 16; o; o >>= 1) acc += __shfl_down_sync(0xffffffffu, acc, o);
    if (lane == 0) g_vA[row] = sigm(a[row] + acc);
}

// ---------------- cheap phase: samples 1..15, rank-2 W, ONE block (R2 version) ----

__device__ __forceinline__ float2 blockdot2(float a, float b) {
    __shared__ float ra[32], rb[32], bc[2];
#pragma unroll
    for (int o = 16; o; o >>= 1) {
        a += __shfl_down_sync(0xffffffffu, a, o);
        b += __shfl_down_sync(0xffffffffu, b, o);
    }
    int w = threadIdx.x >> 5;
    if ((threadIdx.x & 31) == 0) { ra[w] = a; rb[w] = b; }
    __syncthreads();
    if (threadIdx.x == 0) {
        float x = 0.f, y = 0.f;
#pragma unroll
        for (int k = 0; k < 32; k++) { x += ra[k]; y += rb[k]; }
        bc[0] = x; bc[1] = y;
    }
    __syncthreads();
    float2 r; r.x = bc[0]; r.y = bc[1];
    return r;
}

__global__ void __launch_bounds__(CTH, 1) k_cheap(const float* __restrict__ inp,
                                                  float* __restrict__ out) {
    const int tid = threadIdx.x;
    float *qc = g_hA, *sc = g_hB, *qn = g_hC, *sn = g_hD;
    float *rc = g_vA, *vw = g_vB;

    // entry dots for sample 1, step 1: d1 = inputs[0].inputs[1], d2 = vfinal_0.inputs[1]
    float2 dv;
    {
        float a1 = 0.f, a2 = 0.f;
        const float* x0 = inp;
        const float* x1 = inp + FLAT;
        for (int k = tid; k < FLAT; k += CTH) {
            float b_ = x1[k];
            a1 += x0[k] * b_;
            a2 += rc[k] * b_;
        }
        dv = blockdot2(a1, a2);
    }

    for (int i = 1; i < NS; i++) {
        const float* p  = inp + (size_t)(i - 1) * FLAT;   // v_init of prev sample
        const float* pn = inp + (size_t)i * FLAT;         // v_init of this sample
        const float* xn = inp + (size_t)(i + 1) * FLAT;   // next v_init (guarded)
        for (int t = 1; t <= KST; t++) {
            // ---- h phase: h = sigm(LR*(q*(1+d1) - s*(1+d2))); dots q.h, s.h inline
            float c1 = 1.f + dv.x, c2 = 1.f + dv.y;
            float a3 = 0.f, a4 = 0.f;
            float* ht = (t == 1) ? qn : ((t == KST) ? sn : (float*)0);
#pragma unroll
            for (int jj = 0; jj < HID / CTH; jj++) {
                int j = tid + jj * CTH;
                float qj = qc[j], sj = sc[j];
                float h = sigm(LRf * (qj * c1 - sj * c2));
                if (ht) ht[j] = h;
                a3 += qj * h;
                a4 += sj * h;
            }
            float2 dh = blockdot2(a3, a4);

            // ---- v phase: v = sigm(LR*(p*(1+d3) - r*(1+d4))); next-step dots inline
            float c3 = 1.f + dh.x, c4 = 1.f + dh.y;
            float a1 = 0.f, a2 = 0.f;
            if (t < KST) {
#pragma unroll
                for (int kk = 0; kk < FLAT / CTH; kk++) {
                    int k = tid + kk * CTH;
                    float pk = p[k], rk = rc[k];
                    float v = sigm(LRf * (pk * c3 - rk * c4));
                    a1 += pk * v;          // p.v for next step
                    a2 += rk * v;          // r.v for next step
                }
            } else if (i < NS - 1) {
#pragma unroll
                for (int kk = 0; kk < FLAT / CTH; kk++) {
                    int k = tid + kk * CTH;
                    float pk = p[k], rk = rc[k];
                    float v = sigm(LRf * (pk * c3 - rk * c4));
                    vw[k] = v;                         // vfinal_i -> r for next sample
                    float xnk = xn[k];
                    a1 += pn[k] * xnk;                 // inputs[i].inputs[i+1]
                    a2 += v * xnk;                     // vfinal_i.inputs[i+1]
                }
            } else {
#pragma unroll
                for (int kk = 0; kk < FLAT / CTH; kk++) {
                    int k = tid + kk * CTH;
                    float pk = p[k], rk = rc[k];
                    float v = sigm(LRf * (pk * c3 - rk * c4));
                    out[k] = v;                        // final reconstruction
                }
            }
            dv = blockdot2(a1, a2);
        }
        // rotate buffers for next sample
        float* tmp;
        tmp = qc; qc = qn; qn = tmp;
        tmp = sc; sc = sn; sn = tmp;
        tmp = rc; rc = vw; vw = tmp;
    }
}

// ---------------- launch ----------------

extern "C" void kernel_launch(void* const* d_in, const int* in_sizes, int n_in,
                              void* d_out, int out_size) {
    const float* inp = (const float*)d_in[0];  // (16, 64, 64, 3) = 16 x 12288
    const float* W   = (const float*)d_in[1];  // (12288, 4096)
    const float* a   = (const float*)d_in[2];  // (12288, 1)
    const float* b   = (const float*)d_in[3];  // (4096, 1)
    float* out = (float*)d_out;                // (12288, 1)

    float* vA = 0;
    cudaGetSymbolAddress((void**)&vA, g_vA);

    dim3 gT(HID / 512, RCH);
    for (int s = 0; s < KST; s++) {
        const float* v = (s == 0) ? inp : vA;
        k_gemvT<<<gT, 256>>>(W, v);
        k_hred<<<HID / 256, 256>>>(b, (s == 0) ? 1 : ((s == KST - 1) ? 2 : 0));
        k_gemv<<<FLAT / 16, 512>>>(W, a);
    }
    k_cheap<<<1, CTH>>>(inp, out);
}

// round 8
// speedup vs baseline: 1.4489x; 1.4489x over previous
#include <cuda_runtime.h>
#include <cuda_fp16.h>

#define FLAT 12288
#define HID  4096
#define NS   16
#define KST  4
#define LRf  0.01f
#define RCH  96          // row chunks for W^T v partials
#define ROWS_PER_CH 128  // RCH * ROWS_PER_CH == FLAT
#define CTH  1024        // cheap-phase threads (single block)

// ---------------- device scratch (static, no runtime allocation) ----------------
__device__ __half g_Wh[(size_t)FLAT * HID];  // fp16 copy of W (96 MB)
__device__ float g_part[RCH * HID];   // gemvT partial column sums
__device__ float g_h[HID];            // dense-phase working h
__device__ float g_hA[HID];           // hinit_0 (q)
__device__ float g_hB[HID];           // hfinal_0 (s)
__device__ float g_hC[HID];           // pong q
__device__ float g_hD[HID];           // pong s
__device__ float g_vA[FLAT];          // vfinal_0 / r ping
__device__ float g_vB[FLAT];          // r pong

__device__ __forceinline__ float sigm(float x) { return 1.f / (1.f + __expf(-x)); }

// ---------------- W -> fp16 conversion (once per launch, ~45us) ----------------
__global__ void k_conv(const float* __restrict__ W) {
    size_t i = (size_t)blockIdx.x * blockDim.x + threadIdx.x;   // float4 index
    float4 w = ((const float4*)W)[i];
    __half2 h0 = __floats2half2_rn(w.x, w.y);
    __half2 h1 = __floats2half2_rn(w.z, w.w);
    uint2 o;
    o.x = *reinterpret_cast<unsigned*>(&h0);
    o.y = *reinterpret_cast<unsigned*>(&h1);
    ((uint2*)g_Wh)[i] = o;
}

// ---------------- dense phase: sample 0 with fp16 W ----------------

// partial column sums of W^T v: 256 threads x half2 (512 cols per block),
// blockIdx.y = 128-row chunk. grid (8, 96) = 768 blocks.
__global__ void k_gemvT(const float* __restrict__ v) {
    __shared__ float sv[ROWS_PER_CH];
    int r0 = blockIdx.y * ROWS_PER_CH;
    if (threadIdx.x < ROWS_PER_CH) sv[threadIdx.x] = v[r0 + threadIdx.x];
    __syncthreads();
    int col2 = blockIdx.x * 256 + threadIdx.x;      // half2 column index
    const __half2* Wp = (const __half2*)g_Wh + (size_t)r0 * (HID / 2) + col2;
    float ax = 0.f, ay = 0.f;
#pragma unroll 8
    for (int r = 0; r < ROWS_PER_CH; r++) {
        float2 w = __half22float2(Wp[(size_t)r * (HID / 2)]);
        float s = sv[r];
        ax += w.x * s;
        ay += w.y * s;
    }
    float2 o; o.x = ax; o.y = ay;
    ((float2*)g_part)[blockIdx.y * (HID / 2) + col2] = o;
}

// reduce partials + bias + sigmoid -> g_h; optionally save hinit/hfinal
__global__ void k_hred(const float* __restrict__ b, int save) {
    int j = blockIdx.x * 256 + threadIdx.x;
    float s = b[j];
#pragma unroll 8
    for (int r = 0; r < RCH; r++) s += g_part[r * HID + j];
    float h = sigm(s);
    g_h[j] = h;
    if (save == 1) g_hA[j] = h;        // hinit_0 (q for sample 1)
    else if (save == 2) g_hB[j] = h;   // hfinal_0 (s for sample 1)
}

// v = sigmoid(a + W h): one warp per row, 16 rows per 512-thread block
__global__ void k_gemv(const float* __restrict__ a) {
    __shared__ float sh[HID];
    for (int k = threadIdx.x; k < HID; k += blockDim.x) sh[k] = g_h[k];
    __syncthreads();
    int warp = threadIdx.x >> 5, lane = threadIdx.x & 31;
    int row = blockIdx.x * 16 + warp;
    const uint2* Wr = (const uint2*)(g_Wh + (size_t)row * HID);   // 4 halves/load
    float acc = 0.f;
#pragma unroll 8
    for (int i = lane; i < HID / 4; i += 32) {
        uint2 wv = Wr[i];
        float2 f0 = __half22float2(*reinterpret_cast<__half2*>(&wv.x));
        float2 f1 = __half22float2(*reinterpret_cast<__half2*>(&wv.y));
        float4 h4 = *(const float4*)&sh[4 * i];
        acc += f0.x * h4.x + f0.y * h4.y + f1.x * h4.z + f1.y * h4.w;
    }
#pragma unroll
    for (int o = 16; o; o >>= 1) acc += __shfl_down_sync(0xffffffffu, acc, o);
    if (lane == 0) g_vA[row] = sigm(a[row] + acc);
}

// ---------------- cheap phase: samples 1..15, rank-2 W, ONE block (proven R2) ----

__device__ __forceinline__ float2 blockdot2(float a, float b) {
    __shared__ float ra[32], rb[32], bc[2];
#pragma unroll
    for (int o = 16; o; o >>= 1) {
        a += __shfl_down_sync(0xffffffffu, a, o);
        b += __shfl_down_sync(0xffffffffu, b, o);
    }
    int w = threadIdx.x >> 5;
    if ((threadIdx.x & 31) == 0) { ra[w] = a; rb[w] = b; }
    __syncthreads();
    if (threadIdx.x == 0) {
        float x = 0.f, y = 0.f;
#pragma unroll
        for (int k = 0; k < 32; k++) { x += ra[k]; y += rb[k]; }
        bc[0] = x; bc[1] = y;
    }
    __syncthreads();
    float2 r; r.x = bc[0]; r.y = bc[1];
    return r;
}

__global__ void __launch_bounds__(CTH, 1) k_cheap(const float* __restrict__ inp,
                                                  float* __restrict__ out) {
    const int tid = threadIdx.x;
    float *qc = g_hA, *sc = g_hB, *qn = g_hC, *sn = g_hD;
    float *rc = g_vA, *vw = g_vB;

    // entry dots for sample 1, step 1: d1 = inputs[0].inputs[1], d2 = vfinal_0.inputs[1]
    float2 dv;
    {
        float a1 = 0.f, a2 = 0.f;
        const float* x0 = inp;
        const float* x1 = inp + FLAT;
        for (int k = tid; k < FLAT; k += CTH) {
            float b_ = x1[k];
            a1 += x0[k] * b_;
            a2 += rc[k] * b_;
        }
        dv = blockdot2(a1, a2);
    }

    for (int i = 1; i < NS; i++) {
        const float* p  = inp + (size_t)(i - 1) * FLAT;   // v_init of prev sample
        const float* pn = inp + (size_t)i * FLAT;         // v_init of this sample
        const float* xn = pn + FLAT;                      // next v_init (guarded)
        for (int t = 1; t <= KST; t++) {
            // ---- h phase: h = sigm(LR*(q*(1+d1) - s*(1+d2))); dots q.h, s.h inline
            float c1 = 1.f + dv.x, c2 = 1.f + dv.y;
            float a3 = 0.f, a4 = 0.f;
            float* ht = (t == 1) ? qn : ((t == KST) ? sn : (float*)0);
#pragma unroll
            for (int jj = 0; jj < HID / CTH; jj++) {
                int j = tid + jj * CTH;
                float qj = qc[j], sj = sc[j];
                float h = sigm(LRf * (qj * c1 - sj * c2));
                if (ht) ht[j] = h;
                a3 += qj * h;
                a4 += sj * h;
            }
            float2 dh = blockdot2(a3, a4);

            // ---- v phase: v = sigm(LR*(p*(1+d3) - r*(1+d4))); next-step dots inline
            float c3 = 1.f + dh.x, c4 = 1.f + dh.y;
            float a1 = 0.f, a2 = 0.f;
            if (t < KST) {
#pragma unroll
                for (int kk = 0; kk < FLAT / CTH; kk++) {
                    int k = tid + kk * CTH;
                    float pk = p[k], rk = rc[k];
                    float v = sigm(LRf * (pk * c3 - rk * c4));
                    a1 += pk * v;          // p.v for next step
                    a2 += rk * v;          // r.v for next step
                }
            } else if (i < NS - 1) {
#pragma unroll
                for (int kk = 0; kk < FLAT / CTH; kk++) {
                    int k = tid + kk * CTH;
                    float pk = p[k], rk = rc[k];
                    float v = sigm(LRf * (pk * c3 - rk * c4));
                    vw[k] = v;                         // vfinal_i -> r for next sample
                    float xnk = xn[k];
                    a1 += pn[k] * xnk;                 // inputs[i].inputs[i+1]
                    a2 += v * xnk;                     // vfinal_i.inputs[i+1]
                }
            } else {
#pragma unroll
                for (int kk = 0; kk < FLAT / CTH; kk++) {
                    int k = tid + kk * CTH;
                    float pk = p[k], rk = rc[k];
                    float v = sigm(LRf * (pk * c3 - rk * c4));
                    out[k] = v;                        // final reconstruction
                }
            }
            dv = blockdot2(a1, a2);
        }
        // rotate buffers for next sample
        float* tmp;
        tmp = qc; qc = qn; qn = tmp;
        tmp = sc; sc = sn; sn = tmp;
        tmp = rc; rc = vw; vw = tmp;
    }
}

// ---------------- launch ----------------

extern "C" void kernel_launch(void* const* d_in, const int* in_sizes, int n_in,
                              void* d_out, int out_size) {
    const float* inp = (const float*)d_in[0];  // (16, 64, 64, 3) = 16 x 12288
    const float* W   = (const float*)d_in[1];  // (12288, 4096)
    const float* a   = (const float*)d_in[2];  // (12288, 1)
    const float* b   = (const float*)d_in[3];  // (4096, 1)
    float* out = (float*)d_out;                // (12288, 1)

    float* vA = 0;
    cudaGetSymbolAddress((void**)&vA, g_vA);

    k_conv<<<(int)(((size_t)FLAT * HID / 4) / 256), 256>>>(W);

    dim3 gT(HID / 512, RCH);
    for (int s = 0; s < KST; s++) {
        const float* v = (s == 0) ? inp : vA;
        k_gemvT<<<gT, 256>>>(v);
        k_hred<<<HID / 256, 256>>>(b, (s == 0) ? 1 : ((s == KST - 1) ? 2 : 0));
        k_gemv<<<FLAT / 16, 512>>>(a);
    }
    k_cheap<<<1, CTH>>>(inp, out);
}

// round 10
// speedup vs baseline: 1.4577x; 1.0061x over previous
#include <cuda_runtime.h>
#include <cuda_fp16.h>

#define FLAT 12288
#define HID  4096
#define NS   16
#define KST  4
#define LRf  0.01f
#define RCH  96          // row chunks for W^T v partials
#define ROWS_PER_CH 128  // RCH * ROWS_PER_CH == FLAT
#define CTH  1024        // cheap-phase threads (single block)

// ---------------- device scratch (static, no runtime allocation) ----------------
__device__ __half g_Wh[(size_t)FLAT * HID];  // fp16 copy of W (96 MB)
__device__ float g_part[RCH * HID];   // gemvT partial column sums
__device__ float g_h[HID];            // dense-phase working h
__device__ float g_hA[HID];           // hinit_0 (q)
__device__ float g_hB[HID];           // hfinal_0 (s)
__device__ float g_hC[HID];           // pong q
__device__ float g_hD[HID];           // pong s
__device__ float g_vA[FLAT];          // vfinal_0 / r ping
__device__ float g_vB[FLAT];          // r pong

__device__ __forceinline__ float sigm(float x) { return 1.f / (1.f + __expf(-x)); }

// ---------------- dense phase: sample 0 ----------------

// Pass 1 of gemvT, fused with W->fp16 conversion: reads fp32 W (200MB) once,
// emits fp16 copy (100MB) and the partial column sums in the same sweep.
__global__ void k_gemvT_conv(const float* __restrict__ W, const float* __restrict__ v) {
    __shared__ float sv[ROWS_PER_CH];
    int r0 = blockIdx.y * ROWS_PER_CH;
    if (threadIdx.x < ROWS_PER_CH) sv[threadIdx.x] = v[r0 + threadIdx.x];
    __syncthreads();
    int col2 = blockIdx.x * 256 + threadIdx.x;      // float2/half2 column index
    const float2* Wp = (const float2*)W + (size_t)r0 * (HID / 2) + col2;
    __half2* Whp = (__half2*)g_Wh + (size_t)r0 * (HID / 2) + col2;
    float ax = 0.f, ay = 0.f;
#pragma unroll 8
    for (int r = 0; r < ROWS_PER_CH; r++) {
        float2 w = Wp[(size_t)r * (HID / 2)];
        Whp[(size_t)r * (HID / 2)] = __floats2half2_rn(w.x, w.y);
        float s = sv[r];
        ax += w.x * s;
        ay += w.y * s;
    }
    float2 o; o.x = ax; o.y = ay;
    ((float2*)g_part)[blockIdx.y * (HID / 2) + col2] = o;
}

// Passes 2..4: fp16 W. 256 threads x half2 (512 cols per block), grid (8, 96).
__global__ void k_gemvT(const float* __restrict__ v) {
    __shared__ float sv[ROWS_PER_CH];
    int r0 = blockIdx.y * ROWS_PER_CH;
    if (threadIdx.x < ROWS_PER_CH) sv[threadIdx.x] = v[r0 + threadIdx.x];
    __syncthreads();
    int col2 = blockIdx.x * 256 + threadIdx.x;      // half2 column index
    const __half2* Wp = (const __half2*)g_Wh + (size_t)r0 * (HID / 2) + col2;
    float ax = 0.f, ay = 0.f;
#pragma unroll 8
    for (int r = 0; r < ROWS_PER_CH; r++) {
        float2 w = __half22float2(Wp[(size_t)r * (HID / 2)]);
        float s = sv[r];
        ax += w.x * s;
        ay += w.y * s;
    }
    float2 o; o.x = ax; o.y = ay;
    ((float2*)g_part)[blockIdx.y * (HID / 2) + col2] = o;
}

// reduce partials + bias + sigmoid -> g_h; optionally save hinit/hfinal
__global__ void k_hred(const float* __restrict__ b, int save) {
    int j = blockIdx.x * 256 + threadIdx.x;
    float s = b[j];
#pragma unroll 8
    for (int r = 0; r < RCH; r++) s += g_part[r * HID + j];
    float h = sigm(s);
    g_h[j] = h;
    if (save == 1) g_hA[j] = h;        // hinit_0 (q for sample 1)
    else if (save == 2) g_hB[j] = h;   // hfinal_0 (s for sample 1)
}

// v = sigmoid(a + W h): one warp per row, 16 rows per 512-thread block.
// uint4 loads = 8 halves per LDG (16B) for higher bytes-in-flight.
__global__ void k_gemv(const float* __restrict__ a) {
    __shared__ float sh[HID];
    for (int k = threadIdx.x; k < HID; k += blockDim.x) sh[k] = g_h[k];
    __syncthreads();
    int warp = threadIdx.x >> 5, lane = threadIdx.x & 31;
    int row = blockIdx.x * 16 + warp;
    const uint4* Wr = (const uint4*)(g_Wh + (size_t)row * HID);   // 8 halves/load
    float acc = 0.f;
#pragma unroll 8
    for (int i = lane; i < HID / 8; i += 32) {
        uint4 wv = Wr[i];
        float2 f0 = __half22float2(*reinterpret_cast<__half2*>(&wv.x));
        float2 f1 = __half22float2(*reinterpret_cast<__half2*>(&wv.y));
        float2 f2 = __half22float2(*reinterpret_cast<__half2*>(&wv.z));
        float2 f3 = __half22float2(*reinterpret_cast<__half2*>(&wv.w));
        float4 h0 = *(const float4*)&sh[8 * i];
        float4 h1 = *(const float4*)&sh[8 * i + 4];
        acc += f0.x * h0.x + f0.y * h0.y + f1.x * h0.z + f1.y * h0.w;
        acc += f2.x * h1.x + f2.y * h1.y + f3.x * h1.z + f3.y * h1.w;
    }
#pragma unroll
    for (int o = 16; o; o >>= 1) acc += __shfl_down_sync(0xffffffffu, acc, o);
    if (lane == 0) g_vA[row] = sigm(a[row] + acc);
}

// ---------------- cheap phase: samples 1..15, rank-2 W, ONE block ----------------

// two-stage shuffle reduction: no serial 32-load chain on thread0
__device__ __forceinline__ float2 blockdot2(float a, float b) {
    __shared__ float ra[32], rb[32], bc[2];
#pragma unroll
    for (int o = 16; o; o >>= 1) {
        a += __shfl_down_sync(0xffffffffu, a, o);
        b += __shfl_down_sync(0xffffffffu, b, o);
    }
    int w = threadIdx.x >> 5;
    if ((threadIdx.x & 31) == 0) { ra[w] = a; rb[w] = b; }
    __syncthreads();
    if (threadIdx.x < 32) {
        float x = ra[threadIdx.x], y = rb[threadIdx.x];
#pragma unroll
        for (int o = 16; o; o >>= 1) {
            x += __shfl_down_sync(0xffffffffu, x, o);
            y += __shfl_down_sync(0xffffffffu, y, o);
        }
        if (threadIdx.x == 0) { bc[0] = x; bc[1] = y; }
    }
    __syncthreads();
    float2 r; r.x = bc[0]; r.y = bc[1];
    return r;
}

__global__ void __launch_bounds__(CTH, 1) k_cheap(const float* __restrict__ inp,
                                                  float* __restrict__ out) {
    const int tid = threadIdx.x;
    float *qc = g_hA, *sc = g_hB, *qn = g_hC, *sn = g_hD;
    float *rc = g_vA, *vw = g_vB;

    // entry dots for sample 1, step 1: d1 = inputs[0].inputs[1], d2 = vfinal_0.inputs[1]
    float2 dv;
    {
        float a1 = 0.f, a2 = 0.f;
        const float* x0 = inp;
        const float* x1 = inp + FLAT;
        for (int k = tid; k < FLAT; k += CTH) {
            float b_ = x1[k];
            a1 += x0[k] * b_;
            a2 += rc[k] * b_;
        }
        dv = blockdot2(a1, a2);
    }

    for (int i = 1; i < NS; i++) {
        const float* p  = inp + (size_t)(i - 1) * FLAT;   // v_init of prev sample
        const float* pn = inp + (size_t)i * FLAT;         // v_init of this sample
        const float* xn = pn + FLAT;                      // next v_init (guarded)
        for (int t = 1; t <= KST; t++) {
            // ---- h phase: h = sigm(LR*(q*(1+d1) - s*(1+d2))); dots q.h, s.h inline
            float c1 = 1.f + dv.x, c2 = 1.f + dv.y;
            float a3 = 0.f, a4 = 0.f;
            float* ht = (t == 1) ? qn : ((t == KST) ? sn : (float*)0);
#pragma unroll
            for (int jj = 0; jj < HID / CTH; jj++) {
                int j = tid + jj * CTH;
                float qj = qc[j], sj = sc[j];
                float h = sigm(LRf * (qj * c1 - sj * c2));
                if (ht) ht[j] = h;
                a3 += qj * h;
                a4 += sj * h;
            }
            float2 dh = blockdot2(a3, a4);

            // ---- v phase: v = sigm(LR*(p*(1+d3) - r*(1+d4))); next-step dots inline
            float c3 = 1.f + dh.x, c4 = 1.f + dh.y;
            float a1 = 0.f, a2 = 0.f;
            if (t < KST) {
#pragma unroll
                for (int kk = 0; kk < FLAT / CTH; kk++) {
                    int k = tid + kk * CTH;
                    float pk = p[k], rk = rc[k];
                    float v = sigm(LRf * (pk * c3 - rk * c4));
                    a1 += pk * v;          // p.v for next step
                    a2 += rk * v;          // r.v for next step
                }
            } else if (i < NS - 1) {
#pragma unroll
                for (int kk = 0; kk < FLAT / CTH; kk++) {
                    int k = tid + kk * CTH;
                    float pk = p[k], rk = rc[k];
                    float v = sigm(LRf * (pk * c3 - rk * c4));
                    vw[k] = v;                         // vfinal_i -> r for next sample
                    float xnk = xn[k];
                    a1 += pn[k] * xnk;                 // inputs[i].inputs[i+1]
                    a2 += v * xnk;                     // vfinal_i.inputs[i+1]
                }
            } else {
#pragma unroll
                for (int kk = 0; kk < FLAT / CTH; kk++) {
                    int k = tid + kk * CTH;
                    float pk = p[k], rk = rc[k];
                    float v = sigm(LRf * (pk * c3 - rk * c4));
                    out[k] = v;                        // final reconstruction
                }
            }
            dv = blockdot2(a1, a2);
        }
        // rotate buffers for next sample
        float* tmp;
        tmp = qc; qc = qn; qn = tmp;
        tmp = sc; sc = sn; sn = tmp;
        tmp = rc; rc = vw; vw = tmp;
    }
}

// ---------------- launch ----------------

extern "C" void kernel_launch(void* const* d_in, const int* in_sizes, int n_in,
                              void* d_out, int out_size) {
    const float* inp = (const float*)d_in[0];  // (16, 64, 64, 3) = 16 x 12288
    const float* W   = (const float*)d_in[1];  // (12288, 4096)
    const float* a   = (const float*)d_in[2];  // (12288, 1)
    const float* b   = (const float*)d_in[3];  // (4096, 1)
    float* out = (float*)d_out;                // (12288, 1)

    float* vA = 0;
    cudaGetSymbolAddress((void**)&vA, g_vA);

    dim3 gT(HID / 512, RCH);
    for (int s = 0; s < KST; s++) {
        if (s == 0) k_gemvT_conv<<<gT, 256>>>(W, inp);   // fused fp16 conversion
        else        k_gemvT<<<gT, 256>>>(vA);
        k_hred<<<HID / 256, 256>>>(b, (s == 0) ? 1 : ((s == KST - 1) ? 2 : 0));
        k_gemv<<<FLAT / 16, 512>>>(a);
    }
    k_cheap<<<1, CTH>>>(inp, out);
}